// round 3
// baseline (speedup 1.0000x reference)
#include <cuda_runtime.h>

// Scratch: per-node collapsed features (A, B, T, pad). 100000 nodes max.
#define MAX_NODES 100352
__device__ float4 g_node[MAX_NODES];
// Constant pack:
//  [0]=w0 [1]=w1
//  [2..5]=W1[:,0]  [6]=b1[0]
//  [7..10]=W1[:,1] [11]=b1[1]
//  [12..15]=g (W1[j,:2:]·wout[2:])  [16]=gb (b1[2:]·wout[2:])  [17]=bout
__device__ float g_consts[18];

__global__ void precompute_kernel(const float* __restrict__ W1,
                                  const float* __restrict__ b1,
                                  const float* __restrict__ Wout,
                                  const float* __restrict__ bout,
                                  int hidden) {
    __shared__ float red[5][128];
    int k = threadIdx.x;          // one thread per hidden unit (hidden <= 128)
    float wk   = (k < hidden) ? Wout[k] : 0.f;
    float mask = (k >= 2 && k < hidden) ? wk : 0.f;
    #pragma unroll
    for (int j = 0; j < 4; j++)
        red[j][k] = (k < hidden) ? mask * W1[j * hidden + k] : 0.f;
    red[4][k] = (k < hidden) ? mask * b1[k] : 0.f;
    __syncthreads();
    if (k == 0) {
        float sums[5];
        #pragma unroll
        for (int j = 0; j < 5; j++) {
            float s = 0.f;
            for (int t = 0; t < hidden; t++) s += red[j][t];
            sums[j] = s;
        }
        g_consts[0] = Wout[0];
        g_consts[1] = Wout[1];
        #pragma unroll
        for (int j = 0; j < 4; j++) {
            g_consts[2 + j]  = W1[j * hidden + 0];
            g_consts[7 + j]  = W1[j * hidden + 1];
            g_consts[12 + j] = sums[j];
        }
        g_consts[6]  = b1[0];
        g_consts[11] = b1[1];
        g_consts[16] = sums[4];
        g_consts[17] = bout[0];
    }
}

__global__ void node_kernel(const float4* __restrict__ x4,
                            float* __restrict__ out, int n) {
    int i = blockIdx.x * blockDim.x + threadIdx.x;
    if (i >= n) return;
    float c0  = g_consts[0],  c1  = g_consts[1];
    float a0  = g_consts[2],  a1  = g_consts[3],  a2  = g_consts[4],  a3  = g_consts[5];
    float b10 = g_consts[6];
    float d0  = g_consts[7],  d1  = g_consts[8],  d2  = g_consts[9],  d3  = g_consts[10];
    float b11 = g_consts[11];
    float g0  = g_consts[12], g1  = g_consts[13], g2  = g_consts[14], g3  = g_consts[15];
    float gb  = g_consts[16], bo  = g_consts[17];

    float4 xv = x4[i];
    float h0 = fmaf(xv.x, a0, fmaf(xv.y, a1, fmaf(xv.z, a2, fmaf(xv.w, a3, b10))));
    float h1 = fmaf(xv.x, d0, fmaf(xv.y, d1, fmaf(xv.z, d2, fmaf(xv.w, d3, b11))));
    float T  = fmaf(xv.x, g0, fmaf(xv.y, g1, fmaf(xv.z, g2, fmaf(xv.w, g3, gb))));
    float A  = fmaf(h0, c0, h1 * c1);
    float B  = fmaf(h0, c1, -h1 * c0);

    g_node[i] = make_float4(A, B, T, 0.f);
    out[i] = A + T + bo;   // base = h·Wout + bout; edge kernel accumulates on top
}

__global__ void edge_kernel(const int2* __restrict__ edges,
                            const float* __restrict__ phases,
                            float* __restrict__ out, int m) {
    int e = blockIdx.x * blockDim.x + threadIdx.x;
    if (e >= m) return;
    int2 ed = edges[e];
    float s, c;
    __sincosf(phases[e], &s, &c);
    float4 nu = g_node[ed.x];   // source features (rotated by +phase into v)
    float4 nv = g_node[ed.y];   // dest features   (rotated by -phase into u)
    atomicAdd(out + ed.y, fmaf(c, nu.x, fmaf(s,  nu.y, nu.z)));
    atomicAdd(out + ed.x, fmaf(c, nv.x, fmaf(-s, nv.y, nv.z)));
}

extern "C" void kernel_launch(void* const* d_in, const int* in_sizes, int n_in,
                              void* d_out, int out_size) {
    const float* x      = (const float*)d_in[0];
    const int*   edges  = (const int*)  d_in[1];
    const float* W1     = (const float*)d_in[2];
    const float* b1     = (const float*)d_in[3];
    const float* phases = (const float*)d_in[4];
    const float* Wout   = (const float*)d_in[5];
    const float* bout   = (const float*)d_in[6];
    float* out = (float*)d_out;

    int hidden = in_sizes[3];          // 64
    int n = in_sizes[0] / 4;           // nodes (IN_DIM = 4)
    int m = in_sizes[1] / 2;           // edges

    precompute_kernel<<<1, (hidden <= 128 ? 128 : hidden)>>>(W1, b1, Wout, bout, hidden);
    node_kernel<<<(n + 255) / 256, 256>>>((const float4*)x, out, n);
    edge_kernel<<<(m + 255) / 256, 256>>>((const int2*)edges, phases, out, m);
}